// round 1
// baseline (speedup 1.0000x reference)
#include <cuda_runtime.h>
#include <math.h>

#define NB 4
#define Hh 64
#define Ff 10
#define Tt 60
#define Dd 6
#define Bb 2048

// Packed recurrent weights: U4[j*64+h] = (U_i, U_ste, U_c, U_o)[j][h]
__device__ float4 g_U4[Hh * Hh];

__global__ void prep_kernel(const float* __restrict__ Ui, const float* __restrict__ Us,
                            const float* __restrict__ Uc, const float* __restrict__ Uo) {
    int idx = blockIdx.x * blockDim.x + threadIdx.x;
    if (idx < Hh * Hh) g_U4[idx] = make_float4(Ui[idx], Us[idx], Uc[idx], Uo[idx]);
}

__device__ __forceinline__ float hsig(float v) {
    // clip(v/6 + 0.5, 0, 1)
    return __saturatef(fmaf(v, 0.16666667f, 0.5f));
}

__global__ __launch_bounds__(Hh) void sfm_kernel(
    const float* __restrict__ x,
    const float* __restrict__ W_i,   const float* __restrict__ b_i,
    const float* __restrict__ W_ste, const float* __restrict__ b_ste,
    const float* __restrict__ W_fre, const float* __restrict__ U_fre, const float* __restrict__ b_fre,
    const float* __restrict__ W_c,   const float* __restrict__ b_c,
    const float* __restrict__ W_o,   const float* __restrict__ b_o,
    const float* __restrict__ U_a,   const float* __restrict__ b_a,
    const float* __restrict__ W_p,   const float* __restrict__ b_p,
    float* __restrict__ out)
{
    __shared__ float sh_x[NB * Tt * Dd];
    __shared__ float sh_h[2][NB][Hh];
    __shared__ float sh_fre[NB][Ff];
    __shared__ float sh_cs[Tt * Ff];
    __shared__ float sh_sn[Tt * Ff];

    const int h  = threadIdx.x;      // 0..63, owns output column h
    const int b0 = blockIdx.x * NB;  // first batch element of this block

    // Stage x for this block's NB batches into shared (coalesced).
    const float* xg = x + (size_t)b0 * (Tt * Dd);
    for (int i = h; i < NB * Tt * Dd; i += Hh) sh_x[i] = xg[i];

    // Sin/cos table: omega = 2*pi*(t+1)*(f/10) reduced exactly mod 2*pi.
    for (int i = h; i < Tt * Ff; i += Hh) {
        int tt = i / Ff + 1;
        int f  = i % Ff;
        int m  = (tt * f) % Ff;
        float ang = (float)m * 0.62831853071795864769f; // 2*pi/10
        float s, c;
        sincosf(ang, &s, &c);
        sh_cs[i] = c;
        sh_sn[i] = s;
    }

#pragma unroll
    for (int b = 0; b < NB; b++) sh_h[0][b][h] = 0.0f;

    // Per-h input weight columns + biases (registers)
    float wi[Dd], ws[Dd], wc[Dd], wo[Dd];
#pragma unroll
    for (int d = 0; d < Dd; d++) {
        wi[d] = W_i[d * Hh + h];
        ws[d] = W_ste[d * Hh + h];
        wc[d] = W_c[d * Hh + h];
        wo[d] = W_o[d * Hh + h];
    }
    const float bi_ = b_i[h], bs_ = b_ste[h], bc_ = b_c[h], bo_ = b_o[h], ba_ = b_a[h];
    float ua[Ff];
#pragma unroll
    for (int f = 0; f < Ff; f++) ua[f] = U_a[f];

    // fre duty: lanes 0..NB*10-1 each compute one (batch, f) fre output
    const bool fduty = (h < NB * Ff);
    const int  fb = h / Ff;
    const int  ff = h % Ff;
    float wf[Dd];
    float bf = 0.0f;
    if (fduty) {
#pragma unroll
        for (int d = 0; d < Dd; d++) wf[d] = W_fre[d * Ff + ff];
        bf = b_fre[ff];
    }

    // Oscillator state in registers
    float sre[NB][Ff], sim[NB][Ff];
#pragma unroll
    for (int b = 0; b < NB; b++)
#pragma unroll
        for (int f = 0; f < Ff; f++) { sre[b][f] = 0.0f; sim[b][f] = 0.0f; }

    __syncthreads();

    int p = 0;
    for (int t = 0; t < Tt; t++) {
        // Gate pre-activations, initialized with bias + x_t @ W
        float ai[NB], as_[NB], ac[NB], ao[NB];
#pragma unroll
        for (int b = 0; b < NB; b++) {
            const float* xb = &sh_x[(b * Tt + t) * Dd];
            float a0 = bi_, a1 = bs_, a2 = bc_, a3 = bo_;
#pragma unroll
            for (int d = 0; d < Dd; d++) {
                float xv = xb[d];
                a0 = fmaf(xv, wi[d], a0);
                a1 = fmaf(xv, ws[d], a1);
                a2 = fmaf(xv, wc[d], a2);
                a3 = fmaf(xv, wo[d], a3);
            }
            ai[b] = a0; as_[b] = a1; ac[b] = a2; ao[b] = a3;
        }
        float af = 0.0f;
        if (fduty) {
            const float* xb = &sh_x[(fb * Tt + t) * Dd];
            af = bf;
#pragma unroll
            for (int d = 0; d < Dd; d++) af = fmaf(xb[d], wf[d], af);
        }

        // Recurrent matmul: h_prev @ [U_i|U_ste|U_c|U_o] (+ U_fre on fre-duty lanes)
        const float* hb = &sh_h[p][0][0];
#pragma unroll 8
        for (int j = 0; j < Hh; j++) {
            float4 u = g_U4[j * Hh + h];   // coalesced LDG.128, L1-hot
#pragma unroll
            for (int b = 0; b < NB; b++) {
                float hj = hb[b * Hh + j]; // LDS broadcast
                ai[b]  = fmaf(hj, u.x, ai[b]);
                as_[b] = fmaf(hj, u.y, as_[b]);
                ac[b]  = fmaf(hj, u.z, ac[b]);
                ao[b]  = fmaf(hj, u.w, ao[b]);
            }
            if (fduty) af = fmaf(hb[fb * Hh + j], U_fre[j * Ff + ff], af);
        }
        if (fduty) sh_fre[fb][ff] = hsig(af);
        __syncthreads();  // fre visible; all reads of sh_h[p] complete

        // State update + output gate
#pragma unroll
        for (int b = 0; b < NB; b++) {
            float iv   = hsig(ai[b]);
            float stev = hsig(as_[b]);
            float ov   = hsig(ao[b]);
            float cv   = iv * tanhf(ac[b]);
            float acca = ba_;
#pragma unroll
            for (int f = 0; f < Ff; f++) {
                float fv = stev * sh_fre[b][f];
                float cs = sh_cs[t * Ff + f];
                float sn = sh_sn[t * Ff + f];
                float r  = fmaf(fv, sre[b][f], cv * cs);
                float m  = fmaf(fv, sim[b][f], cv * sn);
                sre[b][f] = r;
                sim[b][f] = m;
                float A = fmaf(r, r, m * m);
                acca = fmaf(A, ua[f], acca);
            }
            float av = tanhf(acca);
            sh_h[p ^ 1][b][h] = ov * av;
        }
        __syncthreads();  // new h visible before next step
        p ^= 1;
    }

    // Projection: out[b] = h @ W_p + b_p  (O = 1)
    if (h < NB) {
        float acc = b_p[0];
#pragma unroll 8
        for (int j = 0; j < Hh; j++) acc = fmaf(sh_h[p][h][j], W_p[j], acc);
        out[b0 + h] = acc;
    }
}

extern "C" void kernel_launch(void* const* d_in, const int* in_sizes, int n_in,
                              void* d_out, int out_size) {
    const float* x     = (const float*)d_in[0];
    const float* W_i   = (const float*)d_in[1];
    const float* U_i   = (const float*)d_in[2];
    const float* b_i   = (const float*)d_in[3];
    const float* W_ste = (const float*)d_in[4];
    const float* U_ste = (const float*)d_in[5];
    const float* b_ste = (const float*)d_in[6];
    const float* W_fre = (const float*)d_in[7];
    const float* U_fre = (const float*)d_in[8];
    const float* b_fre = (const float*)d_in[9];
    const float* W_c   = (const float*)d_in[10];
    const float* U_c   = (const float*)d_in[11];
    const float* b_c   = (const float*)d_in[12];
    const float* W_o   = (const float*)d_in[13];
    const float* U_o   = (const float*)d_in[14];
    const float* b_o   = (const float*)d_in[15];
    const float* U_a   = (const float*)d_in[16];
    const float* b_a   = (const float*)d_in[17];
    const float* W_p   = (const float*)d_in[18];
    const float* b_p   = (const float*)d_in[19];

    (void)in_sizes; (void)n_in; (void)out_size;

    prep_kernel<<<(Hh * Hh + 255) / 256, 256>>>(U_i, U_ste, U_c, U_o);
    sfm_kernel<<<Bb / NB, Hh>>>(x, W_i, b_i, W_ste, b_ste, W_fre, U_fre, b_fre,
                                W_c, b_c, W_o, b_o, U_a, b_a, W_p, b_p,
                                (float*)d_out);
}

// round 2
// speedup vs baseline: 1.0095x; 1.0095x over previous
#include <cuda_runtime.h>
#include <math.h>

#define NB 4
#define Hh 64
#define Ff 10
#define Tt 60
#define Dd 6
#define Bb 2048

typedef unsigned long long ull;

// Packed recurrent weights: g_U4[j*64+h] = (U_i, U_ste, U_c, U_o)[j][h]
// As ulonglong2: .x = (U_i,U_ste) f32x2 pair, .y = (U_c,U_o) f32x2 pair.
__device__ __align__(16) float4 g_U4[Hh * Hh];

__global__ void prep_kernel(const float* __restrict__ Ui, const float* __restrict__ Us,
                            const float* __restrict__ Uc, const float* __restrict__ Uo) {
    int idx = blockIdx.x * blockDim.x + threadIdx.x;
    if (idx < Hh * Hh) g_U4[idx] = make_float4(Ui[idx], Us[idx], Uc[idx], Uo[idx]);
}

__device__ __forceinline__ float hsig(float v) {
    return __saturatef(fmaf(v, 0.16666667f, 0.5f));
}

__device__ __forceinline__ ull pack2(float lo, float hi) {
    ull r;
    asm("mov.b64 %0, {%1, %2};" : "=l"(r) : "f"(lo), "f"(hi));
    return r;
}
__device__ __forceinline__ ull fma2(ull a, ull b, ull c) {
    ull d;
    asm("fma.rn.f32x2 %0, %1, %2, %3;" : "=l"(d) : "l"(a), "l"(b), "l"(c));
    return d;
}
__device__ __forceinline__ float2 unpack2(ull v) {
    float lo, hi;
    asm("mov.b64 {%0, %1}, %2;" : "=f"(lo), "=f"(hi) : "l"(v));
    return make_float2(lo, hi);
}

__global__ __launch_bounds__(Hh) void sfm_kernel(
    const float* __restrict__ x,
    const float* __restrict__ W_i,   const float* __restrict__ b_i,
    const float* __restrict__ W_ste, const float* __restrict__ b_ste,
    const float* __restrict__ W_fre, const float* __restrict__ U_fre, const float* __restrict__ b_fre,
    const float* __restrict__ W_c,   const float* __restrict__ b_c,
    const float* __restrict__ W_o,   const float* __restrict__ b_o,
    const float* __restrict__ U_a,   const float* __restrict__ b_a,
    const float* __restrict__ W_p,   const float* __restrict__ b_p,
    float* __restrict__ out)
{
    __shared__ float sh_x[NB * Tt * Dd];
    // h duplicated: sh_h[p][j][b] is a 64-bit (h,h) pair; [j][0..3] is 32B,
    // read as two LDS.128 broadcasts per j.
    __shared__ __align__(16) ull sh_h[2][Hh][NB];
    __shared__ float sh_fre[NB][Ff];
    __shared__ float2 sh_cssn[Tt * Ff];
    __shared__ float sh_Ufre[Hh * Ff];

    const int h  = threadIdx.x;      // 0..63, owns output column h
    const int b0 = blockIdx.x * NB;

    // Stage x (coalesced).
    const float* xg = x + (size_t)b0 * (Tt * Dd);
    for (int i = h; i < NB * Tt * Dd; i += Hh) sh_x[i] = xg[i];

    // U_fre into shared (broadcast-friendly in the j loop).
    for (int i = h; i < Hh * Ff; i += Hh) sh_Ufre[i] = U_fre[i];

    // (cos, sin) table: omega = 2*pi*(t+1)*f/10 reduced exactly mod 2*pi.
    for (int i = h; i < Tt * Ff; i += Hh) {
        int tt = i / Ff + 1;
        int f  = i % Ff;
        int m  = (tt * f) % Ff;
        float ang = (float)m * 0.62831853071795864769f; // 2*pi/10
        float s, c;
        sincosf(ang, &s, &c);
        sh_cssn[i] = make_float2(c, s);
    }

#pragma unroll
    for (int b = 0; b < NB; b++) sh_h[0][h][b] = 0ull;

    // Per-h input weight columns, packed as (i,ste) / (c,o) pairs.
    ull wis[Dd], wco[Dd];
#pragma unroll
    for (int d = 0; d < Dd; d++) {
        wis[d] = pack2(W_i[d * Hh + h], W_ste[d * Hh + h]);
        wco[d] = pack2(W_c[d * Hh + h], W_o[d * Hh + h]);
    }
    const ull bias_is = pack2(b_i[h], b_ste[h]);
    const ull bias_co = pack2(b_c[h], b_o[h]);
    const float ba_ = b_a[h];
    float ua[Ff];
#pragma unroll
    for (int f = 0; f < Ff; f++) ua[f] = U_a[f];

    // fre duty: lanes 0..NB*10-1 compute one (batch, f) fre output each.
    const bool fduty = (h < NB * Ff);
    const int  fb = h / Ff;
    const int  ff = h % Ff;
    float wf[Dd];
    float bf = 0.0f;
    if (fduty) {
#pragma unroll
        for (int d = 0; d < Dd; d++) wf[d] = W_fre[d * Ff + ff];
        bf = b_fre[ff];
    }

    float sre[NB][Ff], sim[NB][Ff];
#pragma unroll
    for (int b = 0; b < NB; b++)
#pragma unroll
        for (int f = 0; f < Ff; f++) { sre[b][f] = 0.0f; sim[b][f] = 0.0f; }

    __syncthreads();

    const ulonglong2* U2 = reinterpret_cast<const ulonglong2*>(g_U4);

    int p = 0;
    for (int t = 0; t < Tt; t++) {
        // acc_is[b] = (pre_i, pre_ste), acc_co[b] = (pre_c, pre_o)
        ull acc_is[NB], acc_co[NB];
#pragma unroll
        for (int b = 0; b < NB; b++) {
            const float* xb = &sh_x[(b * Tt + t) * Dd];
            ull a0 = bias_is, a1 = bias_co;
#pragma unroll
            for (int d = 0; d < Dd; d++) {
                ull xd = pack2(xb[d], xb[d]);
                a0 = fma2(xd, wis[d], a0);
                a1 = fma2(xd, wco[d], a1);
            }
            acc_is[b] = a0; acc_co[b] = a1;
        }
        float af = 0.0f;
        if (fduty) {
            const float* xb = &sh_x[(fb * Tt + t) * Dd];
            af = bf;
#pragma unroll
            for (int d = 0; d < Dd; d++) af = fmaf(xb[d], wf[d], af);
        }

        // Recurrent matmul with packed f32x2 FMAs.
        const ull* hrow = &sh_h[p][0][0];
        const float* hrow_f = (const float*)hrow;  // low half of dup pair = value
#pragma unroll 16
        for (int j = 0; j < Hh; j++) {
            ulonglong2 u = U2[j * Hh + h];                       // LDG.128 (L1-hot)
            ulonglong2 q0 = *(const ulonglong2*)&hrow[j * NB];   // LDS.128 bcast: b0,b1
            ulonglong2 q1 = *(const ulonglong2*)&hrow[j * NB + 2]; // b2,b3
            acc_is[0] = fma2(q0.x, u.x, acc_is[0]);
            acc_co[0] = fma2(q0.x, u.y, acc_co[0]);
            acc_is[1] = fma2(q0.y, u.x, acc_is[1]);
            acc_co[1] = fma2(q0.y, u.y, acc_co[1]);
            acc_is[2] = fma2(q1.x, u.x, acc_is[2]);
            acc_co[2] = fma2(q1.x, u.y, acc_co[2]);
            acc_is[3] = fma2(q1.y, u.x, acc_is[3]);
            acc_co[3] = fma2(q1.y, u.y, acc_co[3]);
            if (fduty) af = fmaf(hrow_f[(j * NB + fb) * 2], sh_Ufre[j * Ff + ff], af);
        }
        if (fduty) sh_fre[fb][ff] = hsig(af);
        __syncthreads();  // fre visible; all reads of sh_h[p] complete

        const float2* cssn = &sh_cssn[t * Ff];
#pragma unroll
        for (int b = 0; b < NB; b++) {
            float2 vis = unpack2(acc_is[b]);
            float2 vco = unpack2(acc_co[b]);
            float iv   = hsig(vis.x);
            float stev = hsig(vis.y);
            float ov   = hsig(vco.y);
            float cv   = iv * tanhf(vco.x);
            float acca = ba_;
#pragma unroll
            for (int f = 0; f < Ff; f++) {
                float fv = stev * sh_fre[b][f];
                float2 cn = cssn[f];
                float r  = fmaf(fv, sre[b][f], cv * cn.x);
                float m  = fmaf(fv, sim[b][f], cv * cn.y);
                sre[b][f] = r;
                sim[b][f] = m;
                acca = fmaf(fmaf(r, r, m * m), ua[f], acca);
            }
            float hv = ov * tanhf(acca);
            sh_h[p ^ 1][h][b] = pack2(hv, hv);
        }
        __syncthreads();  // new h visible before next step
        p ^= 1;
    }

    // Projection: out[b] = h @ W_p + b_p  (O = 1)
    if (h < NB) {
        float acc = b_p[0];
        const float* hf = (const float*)&sh_h[p][0][0];
#pragma unroll 8
        for (int j = 0; j < Hh; j++) acc = fmaf(hf[(j * NB + h) * 2], W_p[j], acc);
        out[b0 + h] = acc;
    }
}

extern "C" void kernel_launch(void* const* d_in, const int* in_sizes, int n_in,
                              void* d_out, int out_size) {
    const float* x     = (const float*)d_in[0];
    const float* W_i   = (const float*)d_in[1];
    const float* U_i   = (const float*)d_in[2];
    const float* b_i   = (const float*)d_in[3];
    const float* W_ste = (const float*)d_in[4];
    const float* U_ste = (const float*)d_in[5];
    const float* b_ste = (const float*)d_in[6];
    const float* W_fre = (const float*)d_in[7];
    const float* U_fre = (const float*)d_in[8];
    const float* b_fre = (const float*)d_in[9];
    const float* W_c   = (const float*)d_in[10];
    const float* U_c   = (const float*)d_in[11];
    const float* b_c   = (const float*)d_in[12];
    const float* W_o   = (const float*)d_in[13];
    const float* U_o   = (const float*)d_in[14];
    const float* b_o   = (const float*)d_in[15];
    const float* U_a   = (const float*)d_in[16];
    const float* b_a   = (const float*)d_in[17];
    const float* W_p   = (const float*)d_in[18];
    const float* b_p   = (const float*)d_in[19];

    (void)in_sizes; (void)n_in; (void)out_size;

    prep_kernel<<<(Hh * Hh + 255) / 256, 256>>>(U_i, U_ste, U_c, U_o);
    sfm_kernel<<<Bb / NB, Hh>>>(x, W_i, b_i, W_ste, b_ste, W_fre, U_fre, b_fre,
                                W_c, b_c, W_o, b_o, U_a, b_a, W_p, b_p,
                                (float*)d_out);
}